// round 11
// baseline (speedup 1.0000x reference)
#include <cuda_runtime.h>
#include <cuda_fp16.h>
#include <cuda_pipeline.h>
#include <mma.h>
#include <math.h>

using namespace nvcuda;

#define VOCAB 5000
#define EMB   512
#define HID   1024
#define GATES 4096
#define BATCH 32
#define SEQ   512
#define MROWS (BATCH*SEQ)   /* 16384 */
#define VPAD  5120          /* 40 * 128 */

#define JPC   8             /* j-columns per CTA in recurrence */
#define NCTA  (HID/JPC)     /* 128 persistent CTAs */
#define RPC   (4*JPC)       /* W_hh rows per CTA = 32 */

// ---------------------------------------------------------------------------
// Static device scratch
// ---------------------------------------------------------------------------
__device__ __half g_emb_hi[VOCAB*EMB];
__device__ __half g_Wih_hi[GATES*EMB];
__device__ __half g_Wih_lo[GATES*EMB];
__device__ __half g_Whh_hi[GATES*HID];
__device__ __half g_Wfc_hi[(size_t)VPAD*HID];
__device__ float  g_xg[(size_t)MROWS*GATES];
__device__ __half g_hs_hi[MROWS*HID];
__device__ __half g_h_hi[2][BATCH*HID];      // double-buffered h (fp16 hi only)

// hierarchical barrier state (reset each call; monotonic within a call)
__device__ unsigned g_cnt[8*64];             // 8 counters, 256B apart
__device__ unsigned g_master;
__device__ volatile unsigned g_gen;

// ---------------------------------------------------------------------------
// Prep
// ---------------------------------------------------------------------------
__device__ __forceinline__ void split1(float f, __half* hi, __half* lo, size_t i) {
    __half h = __float2half_rn(f);
    hi[i] = h;
    lo[i] = __float2half_rn(f - __half2float(h));
}

__global__ void prep_weights(const float* __restrict__ wih,
                             const float* __restrict__ whh,
                             const float* __restrict__ wfc) {
    const size_t stride = (size_t)gridDim.x*blockDim.x;
    for (size_t i = blockIdx.x*blockDim.x + threadIdx.x; i < GATES*EMB; i += stride)
        split1(wih[i], g_Wih_hi, g_Wih_lo, i);
    for (size_t i = blockIdx.x*blockDim.x + threadIdx.x; i < GATES*HID; i += stride)
        g_Whh_hi[i] = __float2half_rn(whh[i]);
    for (size_t i = blockIdx.x*blockDim.x + threadIdx.x; i < (size_t)VPAD*HID; i += stride)
        g_Wfc_hi[i] = __float2half_rn(i < (size_t)VOCAB*HID ? wfc[i] : 0.0f);
}

__global__ void prep_emb_init(const float* __restrict__ emb) {
    const size_t stride = (size_t)gridDim.x*blockDim.x;
    const size_t t0 = blockIdx.x*blockDim.x + threadIdx.x;
    for (size_t i = t0; i < VOCAB*EMB; i += stride)
        g_emb_hi[i] = __float2half_rn(emb[i]);
    for (size_t i = t0; i < BATCH*HID; i += stride)
        g_h_hi[0][i] = __float2half_rn(0.0f);
    if (t0 < 8*64) g_cnt[t0] = 0u;
    if (t0 == 0) { g_master = 0u; g_gen = 0u; }
}

// ---------------------------------------------------------------------------
// Kernel 1: xg = emb[x] @ W_ih^T  (M=16384, N=4096, K=512), 2-pass
// (a_hi*b_hi + a_hi*b_lo).  128x128 tile, 256 threads, KC=32, 2-stage cp.async.
// ---------------------------------------------------------------------------
#define EG_STG 5120                       /* halves per array per stage */
#define EG_SMEM (6*EG_STG*2 + 128*4)

__global__ __launch_bounds__(256) void embed_gemm(const int* __restrict__ x) {
    extern __shared__ __align__(16) char sm[];
    __half* As_hi = (__half*)sm;                 // [2][5120]
    __half* Bs_hi = As_hi + 2*EG_STG;
    __half* Bs_lo = Bs_hi + 2*EG_STG;
    int*    rowidx = (int*)(Bs_lo + 2*EG_STG);

    const int n0 = blockIdx.x * 128;
    const int m0 = blockIdx.y * 128;
    const int tid = threadIdx.x;
    const int warp = tid >> 5;
    const int wm = warp >> 1, wn = warp & 1;

    if (tid < 128) rowidx[tid] = x[m0 + tid];
    __syncthreads();

    wmma::fragment<wmma::accumulator, 16, 16, 16, float> acc[2][4];
    #pragma unroll
    for (int i = 0; i < 2; i++)
        #pragma unroll
        for (int j = 0; j < 4; j++)
            wmma::fill_fragment(acc[i][j], 0.0f);

    auto issue = [&](int st, int k0) {
        const int so = st*EG_STG;
        #pragma unroll
        for (int it = 0; it < 2; it++) {
            const int idx = tid + it*256;
            const int row = idx >> 2, c8 = (idx & 3) * 8;
            const int r = rowidx[row];
            __pipeline_memcpy_async(As_hi + so + row*40 + c8, g_emb_hi + (size_t)r*EMB + k0 + c8, 16);
            const int n = n0 + row;
            __pipeline_memcpy_async(Bs_hi + so + row*40 + c8, g_Wih_hi + (size_t)n*EMB + k0 + c8, 16);
            __pipeline_memcpy_async(Bs_lo + so + row*40 + c8, g_Wih_lo + (size_t)n*EMB + k0 + c8, 16);
        }
        __pipeline_commit();
    };

    auto compute = [&](int st) {
        const int so = st*EG_STG;
        #pragma unroll
        for (int ks = 0; ks < 2; ks++) {
            wmma::fragment<wmma::matrix_a, 16, 16, 16, __half, wmma::row_major> a_hi[2];
            wmma::fragment<wmma::matrix_b, 16, 16, 16, __half, wmma::col_major> b_hi[4], b_lo[4];
            #pragma unroll
            for (int i = 0; i < 2; i++)
                wmma::load_matrix_sync(a_hi[i], As_hi + so + (wm*32 + i*16)*40 + ks*16, 40);
            #pragma unroll
            for (int j = 0; j < 4; j++) {
                wmma::load_matrix_sync(b_hi[j], Bs_hi + so + (wn*64 + j*16)*40 + ks*16, 40);
                wmma::load_matrix_sync(b_lo[j], Bs_lo + so + (wn*64 + j*16)*40 + ks*16, 40);
            }
            #pragma unroll
            for (int i = 0; i < 2; i++)
                #pragma unroll
                for (int j = 0; j < 4; j++) {
                    wmma::mma_sync(acc[i][j], a_hi[i], b_hi[j], acc[i][j]);
                    wmma::mma_sync(acc[i][j], a_hi[i], b_lo[j], acc[i][j]);
                }
        }
    };

    issue(0, 0);
    #pragma unroll 1
    for (int kc = 0; kc < EMB/32 - 1; kc++) {
        issue((kc + 1) & 1, (kc + 1)*32);
        __pipeline_wait_prior(1);
        __syncthreads();
        compute(kc & 1);
        __syncthreads();
    }
    __pipeline_wait_prior(0);
    __syncthreads();
    compute((EMB/32 - 1) & 1);

    #pragma unroll
    for (int i = 0; i < 2; i++)
        #pragma unroll
        for (int j = 0; j < 4; j++)
            wmma::store_matrix_sync(
                g_xg + (size_t)(m0 + wm*32 + i*16)*GATES + n0 + wn*64 + j*16,
                acc[i][j], GATES, wmma::mem_row_major);
}

// ---------------------------------------------------------------------------
// Hierarchical grid barrier (tid0-only polling)
// ---------------------------------------------------------------------------
__device__ __forceinline__ void grid_barrier(int s) {
    __syncthreads();
    if (threadIdx.x == 0) {
        __threadfence();
        const unsigned c = blockIdx.x & 7u;
        if (atomicAdd(&g_cnt[c*64], 1u) == 16u*(unsigned)(s + 1) - 1u) {
            if (atomicAdd(&g_master, 1u) == 8u*(unsigned)(s + 1) - 1u) {
                __threadfence();
                g_gen = (unsigned)(s + 1);
            }
        }
        while (g_gen < (unsigned)(s + 1)) __nanosleep(16);
        __threadfence();
    }
    __syncthreads();
}

// ---------------------------------------------------------------------------
// Kernel 2: persistent LSTM recurrence. 128 CTAs x 512 threads (16 warps).
// Warp (wn, wk): wn = N-half (16 of 32 gate-cols), wk = K-slice (128 of 1024).
// W_hh B-fragments REGISTER-RESIDENT across all 512 steps (8 frags/warp),
// preloaded once via a temporary smem image. Per step: cp.async h (64KB)
// into sH, 16 A-loads + 16 MMAs per warp (2 independent m-chains of 8),
// 8-way k-partials summed in the fused cell update.
// ---------------------------------------------------------------------------
#define SM_HROW2 1048                          /* halves; /8 odd -> LDSM clean */
#define SH_BYTES (32*SM_HROW2*2)               /* 67072 */
#define GSM_FLOATS (8*32*36)                   /* 9216 */
#define SMEM_PERSIST (SH_BYTES + (GSM_FLOATS + 32*JPC + RPC)*4)

__global__ __launch_bounds__(512, 1) void lstm_persist(const float* __restrict__ b_ih,
                                                       const float* __restrict__ b_hh) {
    extern __shared__ __align__(16) char smraw[];
    __half* sH   = (__half*)smraw;               // [32][1048] (W image, then h)
    float*  gsm  = (float*)(smraw + SH_BYTES);   // [8][32][36]
    float*  cst  = gsm + GSM_FLOATS;             // [32][8]
    float*  bias = cst + 32*JPC;                 // [32]

    const int tid  = threadIdx.x;
    const int warp = tid >> 5;
    const int wn   = warp & 1;                   // N-half
    const int wk   = warp >> 1;                  // K-slice 0..7
    const int j0 = blockIdx.x * JPC;

    // row loader mapping: 32 rows, 16 threads/row, 8 int4 (128B) each
    const int lrow = tid >> 4;                   // 0..31
    const int lq   = tid & 15;

    // ---- one-time: W_hh slice image -> sH, then B fragments -> registers
    {
        const __half* src = g_Whh_hi + (size_t)((lrow >> 3)*HID + j0 + (lrow & 7))*HID;
        int4* dst = (int4*)(sH + lrow*SM_HROW2);
        const int4* s4 = (const int4*)src;
        #pragma unroll
        for (int i = 0; i < 8; i++) dst[lq + 16*i] = s4[lq + 16*i];
    }
    if (tid < RPC) {
        int gr = (tid >> 3)*HID + j0 + (tid & 7);
        bias[tid] = b_ih[gr] + b_hh[gr];
    }
    for (int i = tid; i < BATCH*JPC; i += 512) cst[i] = 0.0f;
    __syncthreads();

    wmma::fragment<wmma::matrix_b, 16, 16, 16, __half, wmma::col_major> bfr[8];
    #pragma unroll
    for (int ki = 0; ki < 8; ki++)
        wmma::load_matrix_sync(bfr[ki], sH + (wn*16)*SM_HROW2 + wk*128 + ki*16, SM_HROW2);
    __syncthreads();   // all warps done reading W image; sH now free for h

    #pragma unroll 1
    for (int s = 0; s < SEQ; s++) {
        const int rb = s & 1, wb = rb ^ 1;
        const __half* __restrict__ hc = g_h_hi[rb];
        __half* __restrict__ hn = g_h_hi[wb];

        // xg prefetch for cell update (first 256 threads own the 256 outputs)
        float xv[4];
        if (tid < 256) {
            const int b = tid >> 3;
            const float* xr = g_xg + (size_t)(b*SEQ + s)*GATES + j0 + (tid & 7);
            #pragma unroll
            for (int g = 0; g < 4; g++) xv[g] = __ldg(xr + g*HID);
        }

        // stage h: cp.async 64KB (each thread 8 x 16B)
        {
            const __half* src = hc + lrow*HID;
            #pragma unroll
            for (int i = 0; i < 8; i++)
                __pipeline_memcpy_async(sH + lrow*SM_HROW2 + (lq + 16*i)*8,
                                        src + (lq + 16*i)*8, 16);
            __pipeline_commit();
        }
        __pipeline_wait_prior(0);
        __syncthreads();

        // MMA: 2 independent m-chains of 8, B from registers
        wmma::fragment<wmma::accumulator, 16, 16, 16, float> acc0, acc1;
        wmma::fill_fragment(acc0, 0.0f);
        wmma::fill_fragment(acc1, 0.0f);
        const __half* aB0 = sH + wk*128;
        const __half* aB1 = sH + 16*SM_HROW2 + wk*128;
        #pragma unroll
        for (int ki = 0; ki < 8; ki++) {
            wmma::fragment<wmma::matrix_a, 16, 16, 16, __half, wmma::row_major> a0, a1;
            wmma::load_matrix_sync(a0, aB0 + ki*16, SM_HROW2);
            wmma::load_matrix_sync(a1, aB1 + ki*16, SM_HROW2);
            wmma::mma_sync(acc0, a0, bfr[ki], acc0);
            wmma::mma_sync(acc1, a1, bfr[ki], acc1);
        }
        wmma::store_matrix_sync(gsm + wk*1152 + wn*16,          acc0, 36, wmma::mem_row_major);
        wmma::store_matrix_sync(gsm + wk*1152 + 16*36 + wn*16,  acc1, 36, wmma::mem_row_major);
        __syncthreads();

        // fused cell update: 256 outputs (32 batch x 8 j), 8-way k-reduction
        if (tid < 256) {
            const int b  = tid >> 3;
            const int jj = tid & 7;
            const int j  = j0 + jj;
            float iv = xv[0] + bias[ 0 + jj];
            float fv = xv[1] + bias[ 8 + jj];
            float gv = xv[2] + bias[16 + jj];
            float ov = xv[3] + bias[24 + jj];
            #pragma unroll
            for (int k = 0; k < 8; k++) {
                const float* g = gsm + k*1152 + b*36;
                iv += g[ 0 + jj];
                fv += g[ 8 + jj];
                gv += g[16 + jj];
                ov += g[24 + jj];
            }

            float ig = 1.0f / (1.0f + expf(-iv));
            float fg = 1.0f / (1.0f + expf(-fv));
            float gg = tanhf(gv);
            float og = 1.0f / (1.0f + expf(-ov));

            float c = fg * cst[b*JPC + jj] + ig * gg;
            cst[b*JPC + jj] = c;
            float h = og * tanhf(c);
            __half hh = __float2half_rn(h);

            hn[b*HID + j] = hh;
            g_hs_hi[(size_t)(b*SEQ + s)*HID + j] = hh;
        }
        grid_barrier(s);
    }
}

// ---------------------------------------------------------------------------
// Kernel 3: logits = hs @ W_fc^T + b_fc  (M=16384, N=5120pad, K=1024)
// 128x128 tile, 256 threads, 1-pass fp16, KC=32, 2-stage cp.async pipeline.
// ---------------------------------------------------------------------------
#define FC_STG 5120
#define FC_SMEM (4*FC_STG*2 + 8*384*4)

__global__ __launch_bounds__(256) void fc_gemm(const float* __restrict__ b_fc,
                                               float* __restrict__ out) {
    extern __shared__ __align__(16) char sm[];
    __half* As_hi = (__half*)sm;                 // [2][5120]
    __half* Bs_hi = As_hi + 2*FC_STG;
    float*  Cw    = (float*)(Bs_hi + 2*FC_STG);  // [8][384]

    const int n0 = blockIdx.x * 128;
    const int m0 = blockIdx.y * 128;
    const int tid = threadIdx.x;
    const int warp = tid >> 5;
    const int lane = tid & 31;
    const int wm = warp >> 1, wn = warp & 1;

    wmma::fragment<wmma::accumulator, 16, 16, 16, float> acc[2][4];
    #pragma unroll
    for (int i = 0; i < 2; i++)
        #pragma unroll
        for (int j = 0; j < 4; j++)
            wmma::fill_fragment(acc[i][j], 0.0f);

    auto issue = [&](int st, int k0) {
        const int so = st*FC_STG;
        #pragma unroll
        for (int it = 0; it < 2; it++) {
            const int idx = tid + it*256;
            const int row = idx >> 2, c8 = (idx & 3) * 8;
            __pipeline_memcpy_async(As_hi + so + row*40 + c8,
                                    g_hs_hi + (size_t)(m0 + row)*HID + k0 + c8, 16);
            const int n = n0 + row;
            __pipeline_memcpy_async(Bs_hi + so + row*40 + c8,
                                    g_Wfc_hi + (size_t)n*HID + k0 + c8, 16);
        }
        __pipeline_commit();
    };

    auto compute = [&](int st) {
        const int so = st*FC_STG;
        #pragma unroll
        for (int ks = 0; ks < 2; ks++) {
            wmma::fragment<wmma::matrix_a, 16, 16, 16, __half, wmma::row_major> a_hi[2];
            wmma::fragment<wmma::matrix_b, 16, 16, 16, __half, wmma::col_major> b_hi[4];
            #pragma unroll
            for (int i = 0; i < 2; i++)
                wmma::load_matrix_sync(a_hi[i], As_hi + so + (wm*32 + i*16)*40 + ks*16, 40);
            #pragma unroll
            for (int j = 0; j < 4; j++)
                wmma::load_matrix_sync(b_hi[j], Bs_hi + so + (wn*64 + j*16)*40 + ks*16, 40);
            #pragma unroll
            for (int i = 0; i < 2; i++)
                #pragma unroll
                for (int j = 0; j < 4; j++)
                    wmma::mma_sync(acc[i][j], a_hi[i], b_hi[j], acc[i][j]);
        }
    };

    issue(0, 0);
    #pragma unroll 1
    for (int kc = 0; kc < HID/32 - 1; kc++) {
        issue((kc + 1) & 1, (kc + 1)*32);
        __pipeline_wait_prior(1);
        __syncthreads();
        compute(kc & 1);
        __syncthreads();
    }
    __pipeline_wait_prior(0);
    __syncthreads();
    compute((HID/32 - 1) & 1);

    // epilogue: per-warp staging, add bias, guard VOCAB
    #pragma unroll
    for (int i = 0; i < 2; i++)
        #pragma unroll
        for (int j = 0; j < 4; j++) {
            __syncwarp();
            wmma::store_matrix_sync(Cw + warp*384, acc[i][j], 24, wmma::mem_row_major);
            __syncwarp();
            const int mbase = m0 + wm*32 + i*16;
            const int nbase = n0 + wn*64 + j*16;
            #pragma unroll
            for (int e = 0; e < 8; e++) {
                const int idx = lane*8 + e;
                const int rr = idx >> 4, cc = idx & 15;
                const int v = nbase + cc;
                if (v < VOCAB)
                    out[(size_t)(mbase + rr)*VOCAB + v] = Cw[warp*384 + rr*24 + cc] + b_fc[v];
            }
        }
}

// ---------------------------------------------------------------------------
// Launch (lstm_persist stays the 4th launch for the ncu slot)
// ---------------------------------------------------------------------------
extern "C" void kernel_launch(void* const* d_in, const int* in_sizes, int n_in,
                              void* d_out, int out_size) {
    const int*   x    = (const int*)  d_in[0];
    const float* emb  = (const float*)d_in[1];
    const float* W_ih = (const float*)d_in[2];
    const float* W_hh = (const float*)d_in[3];
    const float* b_ih = (const float*)d_in[4];
    const float* b_hh = (const float*)d_in[5];
    const float* W_fc = (const float*)d_in[6];
    const float* b_fc = (const float*)d_in[7];
    float* out = (float*)d_out;

    (void)in_sizes; (void)n_in; (void)out_size;

    prep_weights<<<1024, 256>>>(W_ih, W_hh, W_fc);      // launch 1
    prep_emb_init<<<1024, 256>>>(emb);                  // launch 2

    cudaFuncSetAttribute(embed_gemm, cudaFuncAttributeMaxDynamicSharedMemorySize, EG_SMEM);
    embed_gemm<<<dim3(GATES/128, MROWS/128), 256, EG_SMEM>>>(x);   // launch 3

    cudaFuncSetAttribute(lstm_persist, cudaFuncAttributeMaxDynamicSharedMemorySize,
                         SMEM_PERSIST);
    lstm_persist<<<NCTA, 512, SMEM_PERSIST>>>(b_ih, b_hh);         // launch 4 (ncu slot)

    cudaFuncSetAttribute(fc_gemm, cudaFuncAttributeMaxDynamicSharedMemorySize, FC_SMEM);
    fc_gemm<<<dim3(VPAD/128, MROWS/128), 256, FC_SMEM>>>(b_fc, out);
}